// round 5
// baseline (speedup 1.0000x reference)
#include <cuda_runtime.h>

// Problem constants
#define B_  512
#define T_  512
#define L_  64
#define H_  512
#define G3  1536           // 3*H
#define XW  575            // T + L - 1 (x row width)

// ---------------------------------------------------------------------------
// Scratch (device globals; no allocation allowed)
// ---------------------------------------------------------------------------
__device__ float g_GI1[(size_t)L_ * B_ * G3];  // precomputed input gates, layer 1: [L][B][3H]
__device__ float g_GH1[B_ * G3];               // hidden gates, layer 1 (current step)
__device__ float g_GI2[B_ * G3];               // input gates, layer 2
__device__ float g_GH2[B_ * G3];               // hidden gates, layer 2
__device__ float g_h1[B_ * H_];
__device__ float g_h2[B_ * H_];

__device__ __forceinline__ float sigf(float v) { return 1.f / (1.f + __expf(-v)); }

// ---------------------------------------------------------------------------
// GEMM body: C[M,1536] = A[M,512] @ W[1536,512]^T + bias
// 64x64 block tile, BK=16, 256 threads, 4x4 per thread.
// WIN=true: A is the x tensor; logical row m=(t*B+b) maps to x[b, t : t+512].
// ---------------------------------------------------------------------------
template <bool WIN>
__device__ __forceinline__ void gemm_body(const float* __restrict__ A,
                                          const float* __restrict__ W,
                                          const float* __restrict__ bias,
                                          float* __restrict__ C)
{
    __shared__ float As[16][64];
    __shared__ float Ws[16][64];

    const int tid = threadIdx.x;
    const int tx  = tid & 15;        // N direction (x4)
    const int ty  = tid >> 4;        // M direction (x4)
    const int m0  = blockIdx.y * 64;
    const int n0  = blockIdx.x * 64;

    const int lr = tid >> 2;         // 0..63: row within tile (loader)
    const int lk = (tid & 3) * 4;    // 0,4,8,12: k offset (loader)

    const float* arow;
    if (WIN) {
        const int m = m0 + lr;
        const int t = m >> 9;        // B_ = 512
        const int b = m & 511;
        arow = A + (size_t)b * XW + t;
    } else {
        arow = A + (size_t)(m0 + lr) * 512;
    }
    const float* wrow = W + (size_t)(n0 + lr) * 512;

    float acc[4][4];
#pragma unroll
    for (int i = 0; i < 4; i++)
#pragma unroll
        for (int j = 0; j < 4; j++) acc[i][j] = 0.f;

    for (int k0 = 0; k0 < 512; k0 += 16) {
        if (WIN) {
            // windows are not 16B aligned (stride 575): scalar loads
#pragma unroll
            for (int i = 0; i < 4; i++) As[lk + i][lr] = arow[k0 + lk + i];
        } else {
            float4 a = *reinterpret_cast<const float4*>(arow + k0 + lk);
            As[lk + 0][lr] = a.x; As[lk + 1][lr] = a.y;
            As[lk + 2][lr] = a.z; As[lk + 3][lr] = a.w;
        }
        {
            float4 w = *reinterpret_cast<const float4*>(wrow + k0 + lk);
            Ws[lk + 0][lr] = w.x; Ws[lk + 1][lr] = w.y;
            Ws[lk + 2][lr] = w.z; Ws[lk + 3][lr] = w.w;
        }
        __syncthreads();

#pragma unroll
        for (int k = 0; k < 16; k++) {
            const float4 av = *reinterpret_cast<const float4*>(&As[k][ty * 4]);
            const float4 wv = *reinterpret_cast<const float4*>(&Ws[k][tx * 4]);
            const float am[4] = {av.x, av.y, av.z, av.w};
            const float wn[4] = {wv.x, wv.y, wv.z, wv.w};
#pragma unroll
            for (int i = 0; i < 4; i++)
#pragma unroll
                for (int j = 0; j < 4; j++) acc[i][j] += am[i] * wn[j];
        }
        __syncthreads();
    }

    const int n = n0 + tx * 4;
    const float4 bv = *reinterpret_cast<const float4*>(bias + n);
#pragma unroll
    for (int i = 0; i < 4; i++) {
        const int m = m0 + ty * 4 + i;
        float4 cv;
        cv.x = acc[i][0] + bv.x;
        cv.y = acc[i][1] + bv.y;
        cv.z = acc[i][2] + bv.z;
        cv.w = acc[i][3] + bv.w;
        *reinterpret_cast<float4*>(C + (size_t)m * G3 + n) = cv;
    }
}

// Phase 1: GI1[t][b][:] = x[b, t:t+512] @ W_ih1^T + b_ih1.  grid (24, 512)
__global__ void __launch_bounds__(256) gemm_win_kernel(const float* __restrict__ x,
                                                       const float* __restrict__ W,
                                                       const float* __restrict__ bias)
{
    gemm_body<true>(x, W, bias, g_GI1);
}

// Initial GH1 = h1 @ W_hh1^T + b_hh1.  grid (24, 8)
__global__ void __launch_bounds__(256) gemm_hh1_kernel(const float* __restrict__ W,
                                                       const float* __restrict__ bias)
{
    gemm_body<false>(g_h1, W, bias, g_GH1);
}

// Per-step batched 3-way GEMM.  grid (24, 8, 3)
//   z=0: GI2      = h1_new @ W_ih2^T + b_ih2
//   z=1: GH2      = h2     @ W_hh2^T + b_hh2
//   z=2: GH1_next = h1_new @ W_hh1^T + b_hh1
__global__ void __launch_bounds__(256) gemm3_step_kernel(const float* __restrict__ Wi2,
                                                         const float* __restrict__ bi2,
                                                         const float* __restrict__ Wh2,
                                                         const float* __restrict__ bh2,
                                                         const float* __restrict__ Wh1,
                                                         const float* __restrict__ bh1)
{
    const float* A;
    const float* W;
    const float* bias;
    float* C;
    switch (blockIdx.z) {
        case 0:  A = g_h1; W = Wi2; bias = bi2; C = g_GI2; break;
        case 1:  A = g_h2; W = Wh2; bias = bh2; C = g_GH2; break;
        default: A = g_h1; W = Wh1; bias = bh1; C = g_GH1; break;
    }
    gemm_body<false>(A, W, bias, C);
}

// GRU gate update, layer 1: h1 <- GRU(GI1[t], GH1, h1).  grid 1024x256
__global__ void gru_update1_kernel(int t)
{
    const int idx = blockIdx.x * blockDim.x + threadIdx.x;   // < B*H
    const int b = idx >> 9;
    const int j = idx & 511;
    const float* gib = g_GI1 + (size_t)t * B_ * G3 + (size_t)b * G3;
    const float* ghb = g_GH1 + (size_t)b * G3;
    const float r = sigf(gib[j] + ghb[j]);
    const float z = sigf(gib[H_ + j] + ghb[H_ + j]);
    const float n = tanhf(gib[2 * H_ + j] + r * ghb[2 * H_ + j]);
    g_h1[idx] = (1.f - z) * n + z * g_h1[idx];
}

// GRU gate update, layer 2: h2 <- GRU(GI2, GH2, h2).  grid 1024x256
__global__ void gru_update2_kernel()
{
    const int idx = blockIdx.x * blockDim.x + threadIdx.x;
    const int b = idx >> 9;
    const int j = idx & 511;
    const float* gib = g_GI2 + (size_t)b * G3;
    const float* ghb = g_GH2 + (size_t)b * G3;
    const float r = sigf(gib[j] + ghb[j]);
    const float z = sigf(gib[H_ + j] + ghb[H_ + j]);
    const float n = tanhf(gib[2 * H_ + j] + r * ghb[2 * H_ + j]);
    g_h2[idx] = (1.f - z) * n + z * g_h2[idx];
}

// y[b, t] = h2[b,:] . W_fc + b_fc.  One warp per b.  grid 64x256
__global__ void y_kernel(const float* __restrict__ W_fc,
                         const float* __restrict__ b_fc,
                         float* __restrict__ ys, int t)
{
    const int w    = (blockIdx.x * blockDim.x + threadIdx.x) >> 5;  // 0..511
    const int lane = threadIdx.x & 31;
    const float* hb = g_h2 + (size_t)w * H_;
    float s = 0.f;
#pragma unroll
    for (int it = 0; it < 4; it++) {
        const int k = it * 128 + lane * 4;
        const float4 hv = *reinterpret_cast<const float4*>(hb + k);
        const float4 wv = *reinterpret_cast<const float4*>(W_fc + k);
        s += hv.x * wv.x + hv.y * wv.y + hv.z * wv.z + hv.w * wv.w;
    }
#pragma unroll
    for (int off = 16; off; off >>= 1) s += __shfl_xor_sync(0xFFFFFFFFu, s, off);
    if (lane == 0) ys[(size_t)w * L_ + t] = s + b_fc[0];
}

// h1/h2 init from inputs.  grid 1024x256
__global__ void init_h_kernel(const float* __restrict__ h1_in,
                              const float* __restrict__ h2_in)
{
    const int i = blockIdx.x * blockDim.x + threadIdx.x;
    g_h1[i] = h1_in[i];
    g_h2[i] = h2_in[i];
}

// Final hidden-state writeback.  grid 1024x256
__global__ void write_h_kernel(float* __restrict__ out)
{
    const int i = blockIdx.x * blockDim.x + threadIdx.x;
    out[B_ * L_ + i] = g_h1[i];
    out[B_ * L_ + B_ * H_ + i] = g_h2[i];
}

// ---------------------------------------------------------------------------
extern "C" void kernel_launch(void* const* d_in, const int* in_sizes, int n_in,
                              void* d_out, int out_size)
{
    const float* x     = (const float*)d_in[0];
    const float* h1_in = (const float*)d_in[1];
    const float* h2_in = (const float*)d_in[2];
    const float* W_ih1 = (const float*)d_in[3];
    const float* W_hh1 = (const float*)d_in[4];
    const float* b_ih1 = (const float*)d_in[5];
    const float* b_hh1 = (const float*)d_in[6];
    const float* W_ih2 = (const float*)d_in[7];
    const float* W_hh2 = (const float*)d_in[8];
    const float* b_ih2 = (const float*)d_in[9];
    const float* b_hh2 = (const float*)d_in[10];
    const float* W_fc  = (const float*)d_in[11];
    const float* b_fc  = (const float*)d_in[12];

    float* out = (float*)d_out;      // [B*L ys] [B*H h1] [B*H h2]
    float* ys  = out;

    const dim3 blk(256);

    // h state init
    init_h_kernel<<<(B_ * H_) / 256, blk>>>(h1_in, h2_in);

    // Phase 1: all layer-1 input projections in one big GEMM (L*B = 32768 rows)
    gemm_win_kernel<<<dim3(G3 / 64, (L_ * B_) / 64), blk>>>(x, W_ih1, b_ih1);

    // GH1 for step 0
    gemm_hh1_kernel<<<dim3(G3 / 64, B_ / 64), blk>>>(W_hh1, b_hh1);

    // Recurrent scan
    for (int t = 0; t < L_; t++) {
        gru_update1_kernel<<<(B_ * H_) / 256, blk>>>(t);
        gemm3_step_kernel<<<dim3(G3 / 64, B_ / 64, 3), blk>>>(W_ih2, b_ih2,
                                                              W_hh2, b_hh2,
                                                              W_hh1, b_hh1);
        gru_update2_kernel<<<(B_ * H_) / 256, blk>>>();
        y_kernel<<<64, blk>>>(W_fc, b_fc, ys, t);
    }

    // Final hidden states
    write_h_kernel<<<(B_ * H_) / 256, blk>>>(out);
}

// round 7
// speedup vs baseline: 2.4669x; 2.4669x over previous
#include <cuda_runtime.h>
#include <cuda_bf16.h>
#include <cstdint>
#include <cstddef>

// ---------------------------------------------------------------------------
// Problem constants
// ---------------------------------------------------------------------------
#define B_  512
#define L_  64
#define H_  512
#define G3  1536            // 3*H
#define XW  575             // T + L - 1
#define KP  1536            // expanded K: [hi(512) | lo(512) | hi(512)]
#define BM  128
#define BN  128
#define BKC 32              // bf16 K per chunk
#define NCH (KP / BKC)      // 48
#define APAD_B 80           // padded smem row stride in bytes (40 bf16)
#define TILE_BYTES (BM * APAD_B)      // 10240
#define SMEM_BYTES (4 * TILE_BYTES)   // A0 W0 A1 W1 = 40960

// ---------------------------------------------------------------------------
// Scratch (device globals; allocation is forbidden)
// ---------------------------------------------------------------------------
__device__ __align__(16) float g_GI1[(size_t)L_ * B_ * G3];
__device__ __align__(16) float g_GH1[B_ * G3];
__device__ __align__(16) float g_GI2[B_ * G3];
__device__ __align__(16) float g_GH2[B_ * G3];
__device__ __align__(16) float g_h1[B_ * H_];
__device__ __align__(16) float g_h2[B_ * H_];

__device__ __align__(16) __nv_bfloat16 g_h1e[B_ * KP];                // [hi|lo|hi]
__device__ __align__(16) __nv_bfloat16 g_h2e[B_ * KP];
__device__ __align__(16) __nv_bfloat16 g_Axp[(size_t)L_ * B_ * KP];   // x windows expanded
__device__ __align__(16) __nv_bfloat16 g_Wih1e[(size_t)G3 * KP];      // [Whi|Whi|Wlo]
__device__ __align__(16) __nv_bfloat16 g_Whh1e[(size_t)G3 * KP];
__device__ __align__(16) __nv_bfloat16 g_Wih2e[(size_t)G3 * KP];
__device__ __align__(16) __nv_bfloat16 g_Whh2e[(size_t)G3 * KP];

// ---------------------------------------------------------------------------
// Helpers
// ---------------------------------------------------------------------------
__device__ __forceinline__ uint32_t s2u(const void* p) {
    return (uint32_t)__cvta_generic_to_shared(p);
}
__device__ __forceinline__ void cpa16(uint32_t dst, const void* src) {
    asm volatile("cp.async.cg.shared.global [%0], [%1], 16;" :: "r"(dst), "l"(src));
}
__device__ __forceinline__ void cpa_commit() {
    asm volatile("cp.async.commit_group;" ::: "memory");
}
template <int N> __device__ __forceinline__ void cpa_wait() {
    asm volatile("cp.async.wait_group %0;" :: "n"(N) : "memory");
}
__device__ __forceinline__ void ldsm4(uint32_t& r0, uint32_t& r1, uint32_t& r2,
                                      uint32_t& r3, uint32_t addr) {
    asm volatile("ldmatrix.sync.aligned.m8n8.x4.shared.b16 {%0,%1,%2,%3}, [%4];"
                 : "=r"(r0), "=r"(r1), "=r"(r2), "=r"(r3) : "r"(addr));
}
__device__ __forceinline__ void mma16816(float* d, const uint32_t* a,
                                         uint32_t b0, uint32_t b1) {
    asm volatile(
        "mma.sync.aligned.m16n8k16.row.col.f32.bf16.bf16.f32 "
        "{%0,%1,%2,%3}, {%4,%5,%6,%7}, {%8,%9}, {%0,%1,%2,%3};"
        : "+f"(d[0]), "+f"(d[1]), "+f"(d[2]), "+f"(d[3])
        : "r"(a[0]), "r"(a[1]), "r"(a[2]), "r"(a[3]), "r"(b0), "r"(b1));
}
__device__ __forceinline__ float sigf(float v) { return 1.f / (1.f + __expf(-v)); }

// ---------------------------------------------------------------------------
// Chunk loader: A tile [128 x 32] + W tile [128 x 32] bf16, 80B-padded rows.
// 512 granules (16B) per tile; 256 threads -> 2 each per tile.
// ---------------------------------------------------------------------------
__device__ __forceinline__ void load_tile(const __nv_bfloat16* __restrict__ A,
                                          const __nv_bfloat16* __restrict__ W,
                                          int m0, int n0, int kc,
                                          uint32_t sA, uint32_t sW, int tid)
{
#pragma unroll
    for (int i = 0; i < 2; i++) {
        const int g  = tid + i * 256;
        const int r  = g >> 2;
        const int cg = g & 3;
        const uint32_t so = (uint32_t)(r * APAD_B + cg * 16);
        cpa16(sA + so, A + (size_t)(m0 + r) * KP + kc * BKC + cg * 8);
        cpa16(sW + so, W + (size_t)(n0 + r) * KP + kc * BKC + cg * 8);
    }
    cpa_commit();
}

// ---------------------------------------------------------------------------
// HMMA GEMM: C[M,1536] = A[M,1536]bf16 @ W[1536,1536]bf16^T + bias (fp32 out)
// mode 0: phase-1 (A=g_Axp -> g_GI1), grid (12, 256, 1)
// mode 1: initial GH1,                grid (12, 4, 1)
// mode 2: per-step 3-way,             grid (12, 4, 3)
// ---------------------------------------------------------------------------
__global__ void __launch_bounds__(256, 2) gemm_mma(int mode,
                                                   const float* __restrict__ b_ih1,
                                                   const float* __restrict__ b_hh1,
                                                   const float* __restrict__ b_ih2,
                                                   const float* __restrict__ b_hh2)
{
    extern __shared__ __align__(128) char smem[];

    const __nv_bfloat16* A;
    const __nv_bfloat16* W;
    const float* bias;
    float* C;
    if (mode == 0)      { A = g_Axp; W = g_Wih1e; bias = b_ih1; C = g_GI1; }
    else if (mode == 1) { A = g_h1e; W = g_Whh1e; bias = b_hh1; C = g_GH1; }
    else {
        switch (blockIdx.z) {
            case 0:  A = g_h1e; W = g_Wih2e; bias = b_ih2; C = g_GI2; break;
            case 1:  A = g_h2e; W = g_Whh2e; bias = b_hh2; C = g_GH2; break;
            default: A = g_h1e; W = g_Whh1e; bias = b_hh1; C = g_GH1; break;
        }
    }

    const int tid  = threadIdx.x;
    const int warp = tid >> 5;
    const int lane = tid & 31;
    const int wm   = warp >> 2;        // 0..1 -> m offset wm*64
    const int wn   = warp & 3;         // 0..3 -> n offset wn*32
    const int m0   = blockIdx.y * BM;
    const int n0   = blockIdx.x * BN;

    const uint32_t sb = s2u(smem);
    // buffers: [A0][W0][A1][W1]
    const uint32_t sA0 = sb;
    const uint32_t sW0 = sb + TILE_BYTES;
    const uint32_t sA1 = sb + 2 * TILE_BYTES;
    const uint32_t sW1 = sb + 3 * TILE_BYTES;

    // per-lane ldmatrix offsets
    // A x4 (one m16 frag): lanes 0-7 rows 0-7 k0 | 8-15 rows 8-15 k0 |
    //                      16-23 rows 0-7 k+8 | 24-31 rows 8-15 k+8
    const uint32_t aoff = (uint32_t)((wm * 64 + (lane & 15)) * APAD_B + (lane >> 4) * 16);
    // B x4 (two n8 frags): g=lane/8: n_add=(g>>1)*8 + lane&7, khalf=(g&1)*8
    const int bg = lane >> 3;
    const uint32_t boff = (uint32_t)((wn * 32 + ((bg >> 1) * 8) + (lane & 7)) * APAD_B
                                     + (bg & 1) * 16);

    float acc[4][4][4];
#pragma unroll
    for (int i = 0; i < 4; i++)
#pragma unroll
        for (int j = 0; j < 4; j++)
#pragma unroll
            for (int e = 0; e < 4; e++) acc[i][j][e] = 0.f;

    load_tile(A, W, m0, n0, 0, sA0, sW0, tid);

#pragma unroll 1
    for (int c = 0; c < NCH; c++) {
        const uint32_t bufA = (c & 1) ? sA1 : sA0;
        const uint32_t bufW = (c & 1) ? sW1 : sW0;
        if (c + 1 < NCH) {
            load_tile(A, W, m0, n0, c + 1, (c & 1) ? sA0 : sA1, (c & 1) ? sW0 : sW1, tid);
            cpa_wait<1>();
        } else {
            cpa_wait<0>();
        }
        __syncthreads();

#pragma unroll
        for (int ks = 0; ks < 2; ks++) {
            uint32_t a[4][4];
            uint32_t b[8];
#pragma unroll
            for (int mi = 0; mi < 4; mi++)
                ldsm4(a[mi][0], a[mi][1], a[mi][2], a[mi][3],
                      bufA + aoff + mi * (16 * APAD_B) + ks * 32);
            ldsm4(b[0], b[1], b[2], b[3], bufW + boff + ks * 32);
            ldsm4(b[4], b[5], b[6], b[7], bufW + boff + 16 * APAD_B + ks * 32);
#pragma unroll
            for (int mi = 0; mi < 4; mi++)
#pragma unroll
                for (int nj = 0; nj < 4; nj++)
                    mma16816(acc[mi][nj], a[mi], b[nj * 2], b[nj * 2 + 1]);
        }
        __syncthreads();
    }

    // Epilogue: fused bias, direct fp32 stores
    const int r    = lane >> 2;
    const int cpos = (lane & 3) * 2;
#pragma unroll
    for (int mi = 0; mi < 4; mi++) {
        const int m = m0 + wm * 64 + mi * 16 + r;
        float* row0 = C + (size_t)m * G3;
        float* row1 = C + (size_t)(m + 8) * G3;
#pragma unroll
        for (int nj = 0; nj < 4; nj++) {
            const int n = n0 + wn * 32 + nj * 8 + cpos;
            const float bx = bias[n];
            const float by = bias[n + 1];
            float2 v0 = make_float2(acc[mi][nj][0] + bx, acc[mi][nj][1] + by);
            float2 v1 = make_float2(acc[mi][nj][2] + bx, acc[mi][nj][3] + by);
            *reinterpret_cast<float2*>(row0 + n) = v0;
            *reinterpret_cast<float2*>(row1 + n) = v1;
        }
    }
}

// ---------------------------------------------------------------------------
// Setup kernels
// ---------------------------------------------------------------------------
__global__ void expand_weights_kernel(const float* __restrict__ Wih1,
                                      const float* __restrict__ Whh1,
                                      const float* __restrict__ Wih2,
                                      const float* __restrict__ Whh2)
{
    const int n = blockIdx.x;       // 0..1535
    const int k = threadIdx.x;      // 0..511
    const float* src;
    __nv_bfloat16* dst;
    switch (blockIdx.y) {
        case 0:  src = Wih1; dst = g_Wih1e; break;
        case 1:  src = Whh1; dst = g_Whh1e; break;
        case 2:  src = Wih2; dst = g_Wih2e; break;
        default: src = Whh2; dst = g_Whh2e; break;
    }
    const float v = src[n * 512 + k];
    const __nv_bfloat16 hi = __float2bfloat16(v);
    const __nv_bfloat16 lo = __float2bfloat16(v - __bfloat162float(hi));
    dst[(size_t)n * KP + k]        = hi;
    dst[(size_t)n * KP + 512 + k]  = hi;
    dst[(size_t)n * KP + 1024 + k] = lo;
}

__global__ void build_axp_kernel(const float* __restrict__ x)
{
    const int m = blockIdx.x;       // t*512 + b
    const int t = m >> 9;
    const int b = m & 511;
    const int k = threadIdx.x;      // 0..511
    const float v = x[(size_t)b * XW + t + k];
    const __nv_bfloat16 hi = __float2bfloat16(v);
    const __nv_bfloat16 lo = __float2bfloat16(v - __bfloat162float(hi));
    __nv_bfloat16* row = g_Axp + (size_t)m * KP;
    row[k]        = hi;
    row[512 + k]  = lo;
    row[1024 + k] = hi;
}

__global__ void init_h_kernel(const float* __restrict__ h1in,
                              const float* __restrict__ h2in)
{
    const int b = blockIdx.x;
    const int j = threadIdx.x;
    const float v1 = h1in[b * H_ + j];
    const float v2 = h2in[b * H_ + j];
    g_h1[b * H_ + j] = v1;
    g_h2[b * H_ + j] = v2;
    const __nv_bfloat16 h1hi = __float2bfloat16(v1);
    const __nv_bfloat16 h1lo = __float2bfloat16(v1 - __bfloat162float(h1hi));
    const __nv_bfloat16 h2hi = __float2bfloat16(v2);
    const __nv_bfloat16 h2lo = __float2bfloat16(v2 - __bfloat162float(h2hi));
    g_h1e[(size_t)b * KP + j]        = h1hi;
    g_h1e[(size_t)b * KP + 512 + j]  = h1lo;
    g_h1e[(size_t)b * KP + 1024 + j] = h1hi;
    g_h2e[(size_t)b * KP + j]        = h2hi;
    g_h2e[(size_t)b * KP + 512 + j]  = h2lo;
    g_h2e[(size_t)b * KP + 1024 + j] = h2hi;
}

// ---------------------------------------------------------------------------
// Elementwise GRU updates (fp32 state + bf16 hi/lo expansion)
// ---------------------------------------------------------------------------
__global__ void ew1_kernel(int t)
{
    const int b = blockIdx.x;
    const int j = threadIdx.x;
    const float* gi = g_GI1 + ((size_t)t * B_ + b) * G3;
    const float* gh = g_GH1 + (size_t)b * G3;
    const float r = sigf(gi[j] + gh[j]);
    const float z = sigf(gi[H_ + j] + gh[H_ + j]);
    const float n = tanhf(gi[2 * H_ + j] + r * gh[2 * H_ + j]);
    const float h = (1.f - z) * n + z * g_h1[b * H_ + j];
    g_h1[b * H_ + j] = h;
    const __nv_bfloat16 hi = __float2bfloat16(h);
    const __nv_bfloat16 lo = __float2bfloat16(h - __bfloat162float(hi));
    g_h1e[(size_t)b * KP + j]        = hi;
    g_h1e[(size_t)b * KP + 512 + j]  = lo;
    g_h1e[(size_t)b * KP + 1024 + j] = hi;
}

__global__ void ew2_kernel(const float* __restrict__ Wfc,
                           const float* __restrict__ bfc,
                           float* __restrict__ ys, int t)
{
    __shared__ float red[16];
    const int b = blockIdx.x;
    const int j = threadIdx.x;
    const float* gi = g_GI2 + (size_t)b * G3;
    const float* gh = g_GH2 + (size_t)b * G3;
    const float r = sigf(gi[j] + gh[j]);
    const float z = sigf(gi[H_ + j] + gh[H_ + j]);
    const float n = tanhf(gi[2 * H_ + j] + r * gh[2 * H_ + j]);
    const float h = (1.f - z) * n + z * g_h2[b * H_ + j];
    g_h2[b * H_ + j] = h;
    const __nv_bfloat16 hi = __float2bfloat16(h);
    const __nv_bfloat16 lo = __float2bfloat16(h - __bfloat162float(hi));
    g_h2e[(size_t)b * KP + j]        = hi;
    g_h2e[(size_t)b * KP + 512 + j]  = lo;
    g_h2e[(size_t)b * KP + 1024 + j] = hi;

    // fused y = h2 . W_fc + b_fc
    float p = h * Wfc[j];
#pragma unroll
    for (int o = 16; o; o >>= 1) p += __shfl_xor_sync(0xFFFFFFFFu, p, o);
    if ((j & 31) == 0) red[j >> 5] = p;
    __syncthreads();
    if (j < 16) {
        float s = red[j];
#pragma unroll
        for (int o = 8; o; o >>= 1) s += __shfl_xor_sync(0xFFFFu, s, o);
        if (j == 0) ys[(size_t)b * L_ + t] = s + bfc[0];
    }
}

__global__ void write_h_kernel(float* __restrict__ out)
{
    const int i = blockIdx.x * blockDim.x + threadIdx.x;
    out[B_ * L_ + i]           = g_h1[i];
    out[B_ * L_ + B_ * H_ + i] = g_h2[i];
}

// ---------------------------------------------------------------------------
extern "C" void kernel_launch(void* const* d_in, const int* in_sizes, int n_in,
                              void* d_out, int out_size)
{
    const float* x     = (const float*)d_in[0];
    const float* h1_in = (const float*)d_in[1];
    const float* h2_in = (const float*)d_in[2];
    const float* W_ih1 = (const float*)d_in[3];
    const float* W_hh1 = (const float*)d_in[4];
    const float* b_ih1 = (const float*)d_in[5];
    const float* b_hh1 = (const float*)d_in[6];
    const float* W_ih2 = (const float*)d_in[7];
    const float* W_hh2 = (const float*)d_in[8];
    const float* b_ih2 = (const float*)d_in[9];
    const float* b_hh2 = (const float*)d_in[10];
    const float* W_fc  = (const float*)d_in[11];
    const float* b_fc  = (const float*)d_in[12];

    float* out = (float*)d_out;     // [B*L ys][B*H h1][B*H h2]

    cudaFuncSetAttribute(gemm_mma, cudaFuncAttributeMaxDynamicSharedMemorySize, SMEM_BYTES);

    // Setup
    expand_weights_kernel<<<dim3(G3, 4), 512>>>(W_ih1, W_hh1, W_ih2, W_hh2);
    init_h_kernel<<<B_, 512>>>(h1_in, h2_in);
    build_axp_kernel<<<L_ * B_, 512>>>(x);

    // Phase 1: all layer-1 input projections (M = 32768)
    gemm_mma<<<dim3(12, 256, 1), 256, SMEM_BYTES>>>(0, b_ih1, b_hh1, b_ih2, b_hh2);

    // Initial GH1
    gemm_mma<<<dim3(12, 4, 1), 256, SMEM_BYTES>>>(1, b_ih1, b_hh1, b_ih2, b_hh2);

    // Recurrent scan
    for (int t = 0; t < L_; t++) {
        ew1_kernel<<<B_, 512>>>(t);
        gemm_mma<<<dim3(12, 4, 3), 256, SMEM_BYTES>>>(2, b_ih1, b_hh1, b_ih2, b_hh2);
        ew2_kernel<<<B_, 512>>>(W_fc, b_fc, out, t);
    }

    write_h_kernel<<<(B_ * H_) / 256, 256>>>(out);
}